// round 2
// baseline (speedup 1.0000x reference)
#include <cuda_runtime.h>
#include <math.h>

#define BB   32
#define TT   400
#define MELD 80
#define LLd  256
#define UU   512
#define MMa  200
#define U4   2048
#define U3   1536
#define BT   (BB*TT)      // 12800
#define NBLK 148
#define NTHR 1024

// ---------------- scratch (device globals: allocation-free) ----------------
__device__ float g_inT [BT*MELD];          // inputs transposed to [T,B,80]
__device__ float g_h1  [BT*UU];            // prenet hidden
__device__ float g_xp  [BT*LLd];           // prenet out [T,B,256]
__device__ float g_keys[BB*MMa*UU];        // attention keys
__device__ float g_xpart[(size_t)BT*U4];   // xp @ lstm_K[:256] + lstm_b
__device__ float g_x   [BT*UU];            // LSTM outputs [T,B,512]
__device__ float g_y1  [BT*UU];            // GRU1 outputs
__device__ float g_xsum[BT*UU];            // x+y1 then x+y1+y2
__device__ float g_xz  [(size_t)BT*U3];    // GRU input projection (reused)
__device__ float g_hstate[BB*UU];
__device__ float g_cstate[BB*UU];
__device__ float g_rec [BB*U4];
__device__ float g_ctx [BB*LLd];
__device__ unsigned g_cnt = 0;
__device__ unsigned g_gen = 0;

// ---------------- software grid barrier ----------------
__device__ __forceinline__ void grid_barrier(unsigned nb)
{
    __syncthreads();
    if (threadIdx.x == 0) {
        __threadfence();
        unsigned my   = atomicAdd(&g_gen, 0u);     // coherent read of generation
        unsigned prev = atomicAdd(&g_cnt, 1u);
        if (prev == nb - 1u) {
            atomicExch(&g_cnt, 0u);
            __threadfence();
            atomicAdd(&g_gen, 1u);
        } else {
            while (atomicAdd(&g_gen, 0u) == my) { __nanosleep(64); }
        }
        __threadfence();
    }
    __syncthreads();
}

__device__ __forceinline__ float sigmoidf_(float x) { return 1.f / (1.f + expf(-x)); }

// ---------------- repack inputs [B,T,80] -> [T,B,80] ----------------
__global__ void repack_inputs(const float* __restrict__ in)
{
    int i = blockIdx.x * blockDim.x + threadIdx.x;
    if (i < BT * MELD) {
        int d = i % MELD;
        int r = i / MELD;          // r = t*32 + b
        int t = r >> 5, b = r & 31;
        g_inT[i] = in[((size_t)b * TT + t) * MELD + d];
    }
}

// ---------------- elementwise add: xsum = x + y1 ----------------
__global__ void add_kernel()
{
    int i = blockIdx.x * blockDim.x + threadIdx.x;
    if (i < BT * UU) g_xsum[i] = g_x[i] + g_y1[i];
}

// ---------------- generic tiled fp32 GEMM: C = op(A[M,K] @ W[K,N] + bias) ----------------
__global__ void gemm_tiled(const float* __restrict__ A, const float* __restrict__ W,
                           const float* __restrict__ bias, float* __restrict__ C,
                           int Mr, int N, int K, int doRelu, int remapTB)
{
    __shared__ float As[16][65];
    __shared__ float Bs[16][64];
    const int tid = threadIdx.x;
    const int tx = tid & 15, ty = tid >> 4;
    const int n0 = blockIdx.x * 64, m0 = blockIdx.y * 64;
    float acc[4][4] = {};

    for (int k0 = 0; k0 < K; k0 += 16) {
#pragma unroll
        for (int i = 0; i < 4; i++) {
            int e = tid + i * 256;
            int r = e >> 4, c = e & 15;
            int gr = m0 + r, gc = k0 + c;
            As[c][r] = (gr < Mr && gc < K) ? A[(size_t)gr * K + gc] : 0.f;
        }
#pragma unroll
        for (int i = 0; i < 4; i++) {
            int e = tid + i * 256;
            int r = e >> 6, c = e & 63;
            int gk = k0 + r, gn = n0 + c;
            Bs[r][c] = (gk < K && gn < N) ? W[(size_t)gk * N + gn] : 0.f;
        }
        __syncthreads();
#pragma unroll
        for (int kk = 0; kk < 16; kk++) {
            float a0 = As[kk][ty*4+0], a1 = As[kk][ty*4+1];
            float a2 = As[kk][ty*4+2], a3 = As[kk][ty*4+3];
            float4 b4 = *(const float4*)&Bs[kk][tx*4];
            acc[0][0] += a0*b4.x; acc[0][1] += a0*b4.y; acc[0][2] += a0*b4.z; acc[0][3] += a0*b4.w;
            acc[1][0] += a1*b4.x; acc[1][1] += a1*b4.y; acc[1][2] += a1*b4.z; acc[1][3] += a1*b4.w;
            acc[2][0] += a2*b4.x; acc[2][1] += a2*b4.y; acc[2][2] += a2*b4.z; acc[2][3] += a2*b4.w;
            acc[3][0] += a3*b4.x; acc[3][1] += a3*b4.y; acc[3][2] += a3*b4.z; acc[3][3] += a3*b4.w;
        }
        __syncthreads();
    }
#pragma unroll
    for (int i = 0; i < 4; i++) {
        int row = m0 + ty*4 + i;
        if (row >= Mr) continue;
#pragma unroll
        for (int j = 0; j < 4; j++) {
            int col = n0 + tx*4 + j;
            if (col >= N) continue;
            float v = acc[i][j] + (bias ? __ldg(bias + col) : 0.f);
            if (doRelu) v = fmaxf(v, 0.f);
            size_t oi;
            if (remapTB) { int t = row >> 5, b = row & 31; oi = ((size_t)b * TT + t) * N + col; }
            else         { oi = (size_t)row * N + col; }
            C[oi] = v;
        }
    }
}

// ---------------- persistent attention-LSTM ----------------
__global__ void __launch_bounds__(NTHR) lstm_attn(
    const float* __restrict__ attended,
    const float* __restrict__ qW, const float* __restrict__ qb,
    const float* __restrict__ vW, const float* __restrict__ vb,
    const float* __restrict__ lstmK, const float* __restrict__ lstmR)
{
    const int tid = threadIdx.x, bid = blockIdx.x;
    __shared__ float h_s[UU];
    __shared__ float q_s[UU];
    __shared__ float v_s[UU];
    __shared__ float qp[NTHR];
    __shared__ float sc[256];
    __shared__ float red[256];
    __shared__ float ctxp[NTHR];
    __shared__ float ctx_s[LLd];
    __shared__ float part[NTHR];
    __shared__ float zz[UU];

    // zero LSTM state
    for (int i = bid * NTHR + tid; i < BB * UU; i += NBLK * NTHR) {
        g_hstate[i] = 0.f; g_cstate[i] = 0.f;
    }
    grid_barrier(NBLK);

    for (int t = 0; t < TT; ++t) {
        // ---- stage 1: attention (blocks 0..31) || rec = h@R + xpart (blocks 32..95) ----
        if (bid < BB) {
            const int b = bid;
            if (tid < UU) { h_s[tid] = __ldcg(&g_hstate[b*UU + tid]); v_s[tid] = __ldg(vW + tid); }
            __syncthreads();
            // q = h @ Wq + qb   (split-k over 2 halves, 1024 threads)
            {
                int u = tid & (UU - 1);
                int half = tid >> 9;
                const float* w = qW + (size_t)(half * 256) * UU + u;
                float acc = 0.f;
#pragma unroll 8
                for (int k = 0; k < 256; ++k) acc += h_s[half*256 + k] * __ldg(w + (size_t)k * UU);
                qp[half*UU + u] = acc;
            }
            __syncthreads();
            if (tid < UU) q_s[tid] = qp[tid] + qp[UU + tid] + __ldg(qb + tid);
            __syncthreads();
            // scores: warp per m
            {
                int w = tid >> 5, lane = tid & 31;
                for (int m = w; m < MMa; m += 32) {
                    const float* krow = g_keys + ((size_t)(b*MMa + m)) * UU;
                    float acc = 0.f;
#pragma unroll
                    for (int j = 0; j < UU/32; ++j) {
                        int u = lane + 32*j;
                        acc += v_s[u] * tanhf(__ldg(krow + u) + q_s[u]);
                    }
                    for (int o = 16; o > 0; o >>= 1) acc += __shfl_down_sync(0xffffffffu, acc, o);
                    if (lane == 0) sc[m] = acc + __ldg(vb);
                }
            }
            __syncthreads();
            // softmax over 200
            if (tid < 256) red[tid] = (tid < MMa) ? sc[tid] : -1e30f;
            __syncthreads();
            for (int s = 128; s > 0; s >>= 1) { if (tid < s) red[tid] = fmaxf(red[tid], red[tid+s]); __syncthreads(); }
            float mx = red[0];
            __syncthreads();
            if (tid < 256) { float e = (tid < MMa) ? expf(sc[tid] - mx) : 0.f; sc[tid] = e; red[tid] = e; }
            __syncthreads();
            for (int s = 128; s > 0; s >>= 1) { if (tid < s) red[tid] += red[tid+s]; __syncthreads(); }
            float inv = 1.f / red[0];
            // ctx = attn @ attended   (4 m-partitions x 256 dims)
            {
                int d = tid & (LLd - 1);
                int prt = tid >> 8;               // 0..3
                const float* att = attended + ((size_t)b * MMa) * LLd + d;
                float acc = 0.f;
                int m0 = prt * 50;
                for (int m = m0; m < m0 + 50; ++m) acc += sc[m] * __ldg(att + (size_t)m * LLd);
                ctxp[tid] = acc;
            }
            __syncthreads();
            if (tid < LLd)
                g_ctx[b*LLd + tid] = (ctxp[tid] + ctxp[LLd+tid] + ctxp[2*LLd+tid] + ctxp[3*LLd+tid]) * inv;
        } else if (bid < BB + 64) {
            const int unit = bid - BB;
            const int b = unit >> 1, nh = unit & 1;
            if (tid < UU) h_s[tid] = __ldcg(&g_hstate[b*UU + tid]);
            __syncthreads();
            int n = nh * 1024 + tid;
            float s = g_xpart[(size_t)t * (BB*U4) + (size_t)b * U4 + n];
            const float* R = lstmR + n;
#pragma unroll 8
            for (int k = 0; k < UU; ++k) s += h_s[k] * __ldg(R + (size_t)k * U4);
            g_rec[b*U4 + n] = s;
        }
        grid_barrier(NBLK);

        // ---- stage 2: z = rec + ctx@K2 -> gates -> h,c ----
        if (bid < 128) {
            const int b = bid >> 2, c = bid & 3;
            if (tid < LLd) ctx_s[tid] = __ldcg(&g_ctx[b*LLd + tid]);
            __syncthreads();
            const float* K2 = lstmK + (size_t)LLd * U4;  // rows 256..511
            {
                int half = tid >> 9;
                int dotid = tid & 511;
                int g = dotid >> 7, up = dotid & 127;
                int n = g*UU + c*128 + up;
                const float* w = K2 + (size_t)(half * 128) * U4 + n;
                float acc = 0.f;
#pragma unroll 8
                for (int d = 0; d < 128; ++d) acc += ctx_s[half*128 + d] * __ldg(w + (size_t)d * U4);
                part[tid] = acc;
            }
            __syncthreads();
            if (tid < UU) {
                int g = tid >> 7, up = tid & 127;
                int n = g*UU + c*128 + up;
                zz[tid] = part[tid] + part[UU + tid] + __ldcg(&g_rec[b*U4 + n]);
            }
            __syncthreads();
            if (tid < 128) {
                int u = c*128 + tid;
                float ig = sigmoidf_(zz[tid]);
                float fg = sigmoidf_(zz[128 + tid]);
                float gg = tanhf   (zz[256 + tid]);
                float og = sigmoidf_(zz[384 + tid]);
                float cold = __ldcg(&g_cstate[b*UU + u]);
                float cn = fg * cold + ig * gg;
                float hn = og * tanhf(cn);
                g_cstate[b*UU + u] = cn;
                g_hstate[b*UU + u] = hn;
                g_x[((size_t)t*BB + b)*UU + u] = hn;
            }
        }
        grid_barrier(NBLK);
    }
}

// ---------------- persistent GRU (reset_after=True) ----------------
__global__ void __launch_bounds__(NTHR) gru_seq(
    const float* __restrict__ R, const float* __restrict__ br,
    const float* __restrict__ xz, float* __restrict__ yout, int accumulate)
{
    const int tid = threadIdx.x, bid = blockIdx.x;
    __shared__ float h_s[UU];
    __shared__ float part[768];
    __shared__ float rec_s[384];

    for (int i = bid * NTHR + tid; i < BB * UU; i += NBLK * NTHR) g_hstate[i] = 0.f;
    grid_barrier(NBLK);

    for (int t = 0; t < TT; ++t) {
        if (bid < 128) {
            const int b = bid >> 2, c = bid & 3;
            if (tid < UU) h_s[tid] = __ldcg(&g_hstate[b*UU + tid]);
            __syncthreads();
            if (tid < 768) {
                int half = (tid >= 384) ? 1 : 0;
                int dotid = tid - half * 384;
                int g = dotid >> 7, up = dotid & 127;
                int n = g*UU + c*128 + up;
                const float* w = R + (size_t)(half * 256) * U3 + n;
                float acc = 0.f;
#pragma unroll 8
                for (int k = 0; k < 256; ++k) acc += h_s[half*256 + k] * __ldg(w + (size_t)k * U3);
                part[tid] = acc;
            }
            __syncthreads();
            if (tid < 384) {
                int g = tid >> 7, up = tid & 127;
                int n = g*UU + c*128 + up;
                rec_s[tid] = part[tid] + part[384 + tid] + __ldg(br + n);
            }
            __syncthreads();
            if (tid < 128) {
                int u = c*128 + tid;
                const float* xzr = xz + ((size_t)t*BB + b) * U3;
                float xz_z = __ldg(xzr + u);
                float xz_r = __ldg(xzr + UU + u);
                float xz_h = __ldg(xzr + 2*UU + u);
                float z = sigmoidf_(xz_z + rec_s[tid]);
                float r = sigmoidf_(xz_r + rec_s[128 + tid]);
                float hh = tanhf(xz_h + r * rec_s[256 + tid]);
                float hn = z * h_s[u] + (1.f - z) * hh;
                g_hstate[b*UU + u] = hn;
                size_t oi = ((size_t)t*BB + b)*UU + u;
                if (accumulate) yout[oi] += hn; else yout[oi] = hn;
            }
        }
        grid_barrier(NBLK);
    }
}

// ---------------- launch ----------------
extern "C" void kernel_launch(void* const* d_in, const int* in_sizes, int n_in,
                              void* d_out, int out_size)
{
    const float* inputs   = (const float*)d_in[0];
    const float* attended = (const float*)d_in[1];
    const float* pre_W1   = (const float*)d_in[2];
    const float* pre_b1   = (const float*)d_in[3];
    const float* pre_W2   = (const float*)d_in[4];
    const float* pre_b2   = (const float*)d_in[5];
    const float* key_W    = (const float*)d_in[6];
    const float* key_b    = (const float*)d_in[7];
    const float* query_W  = (const float*)d_in[8];
    const float* query_b  = (const float*)d_in[9];
    const float* attnv_W  = (const float*)d_in[10];
    const float* attnv_b  = (const float*)d_in[11];
    const float* lstm_K   = (const float*)d_in[12];
    const float* lstm_R   = (const float*)d_in[13];
    const float* lstm_b   = (const float*)d_in[14];
    const float* gru1_K   = (const float*)d_in[15];
    const float* gru1_R   = (const float*)d_in[16];
    const float* gru1_b   = (const float*)d_in[17];
    const float* gru2_K   = (const float*)d_in[18];
    const float* gru2_R   = (const float*)d_in[19];
    const float* gru2_b   = (const float*)d_in[20];
    const float* proj_W   = (const float*)d_in[21];
    float* out = (float*)d_out;

    float *inT, *h1, *xp, *keys, *xpart, *x, *y1, *xsum, *xz;
    cudaGetSymbolAddress((void**)&inT,   g_inT);
    cudaGetSymbolAddress((void**)&h1,    g_h1);
    cudaGetSymbolAddress((void**)&xp,    g_xp);
    cudaGetSymbolAddress((void**)&keys,  g_keys);
    cudaGetSymbolAddress((void**)&xpart, g_xpart);
    cudaGetSymbolAddress((void**)&x,     g_x);
    cudaGetSymbolAddress((void**)&y1,    g_y1);
    cudaGetSymbolAddress((void**)&xsum,  g_xsum);
    cudaGetSymbolAddress((void**)&xz,    g_xz);

    // 1) repack inputs to [T,B,80]
    repack_inputs<<<(BT*MELD + 255)/256, 256>>>(inputs);
    // 2) prenet
    gemm_tiled<<<dim3(UU/64,  BT/64), 256>>>(inT, pre_W1, pre_b1, h1, BT, UU, MELD, 1, 0);
    gemm_tiled<<<dim3(LLd/64, BT/64), 256>>>(h1,  pre_W2, pre_b2, xp, BT, LLd, UU,  1, 0);
    // 3) keys
    gemm_tiled<<<dim3(UU/64, (BB*MMa)/64), 256>>>(attended, key_W, key_b, keys, BB*MMa, UU, LLd, 0, 0);
    // 4) LSTM input part: xp @ lstm_K[:256] + lstm_b
    gemm_tiled<<<dim3(U4/64, BT/64), 256>>>(xp, lstm_K, lstm_b, xpart, BT, U4, LLd, 0, 0);
    // 5) attention LSTM (persistent)
    lstm_attn<<<NBLK, NTHR>>>(attended, query_W, query_b, attnv_W, attnv_b, lstm_K, lstm_R);
    // 6) GRU1: xz = x @ gru1_K + bi1 ; recurrence
    gemm_tiled<<<dim3(U3/64, BT/64), 256>>>(x, gru1_K, gru1_b, xz, BT, U3, UU, 0, 0);
    gru_seq<<<NBLK, NTHR>>>(gru1_R, gru1_b + U3, xz, y1, 0);
    // 7) xsum = x + y1
    add_kernel<<<(BT*UU + 255)/256, 256>>>();
    // 8) GRU2 on xsum, accumulate y2 into xsum
    gemm_tiled<<<dim3(U3/64, BT/64), 256>>>(xsum, gru2_K, gru2_b, xz, BT, U3, UU, 0, 0);
    gru_seq<<<NBLK, NTHR>>>(gru2_R, gru2_b + U3, xz, xsum, 1);
    // 9) mel = relu(xsum @ proj_W), remapped to [B,T,80]
    gemm_tiled<<<dim3((MELD+63)/64, BT/64), 256>>>(xsum, proj_W, nullptr, out, BT, MELD, UU, 1, 1);
}